// round 1
// baseline (speedup 1.0000x reference)
#include <cuda_runtime.h>
#include <math.h>

#define PI_HALF 1.57079632679489662f

// Scratch: pixel-major [N, B] buffers for intermediate activations.
__device__ float g_y0[729 * 128];
__device__ float g_x1[729 * 128];
__device__ float g_y1[81 * 128];
__device__ float g_x2[81 * 128];
__device__ float g_y2[9 * 128];
__device__ float g_x3[9 * 128];

// One block = one output pixel n, one thread = one sample b (B=128).
// Weights for pixel n staged to smem (broadcast reads, conflict-free).
// FIRST=true: x is original [B, S, S] sample-major layout.
// FIRST=false: x is pixel-major [S*S, B] (written by norm_k).
template <bool FIRST>
__global__ void mps_small(const float* __restrict__ x,
                          const float* __restrict__ W0,   // [N,2,1,10]
                          const float* __restrict__ Wm,   // [N,7,10,2,10]
                          const float* __restrict__ Wn,   // [N,10,2]
                          float* __restrict__ y,          // [N,128]
                          int in_side, int out_side)
{
    __shared__ __align__(16) float sWm[1400];
    __shared__ float sW0[20];
    __shared__ float sWn[20];

    const int n = blockIdx.x;
    const int b = threadIdx.x;

    {
        const float* gWm = Wm + n * 1400;
        #pragma unroll
        for (int t = b; t < 1400; t += 128) sWm[t] = gWm[t];
        if (b < 20)       sW0[b]      = W0[n * 20 + b];
        else if (b < 40)  sWn[b - 20] = Wn[n * 20 + (b - 20)];
    }
    __syncthreads();

    const int i = n / out_side;
    const int j = n - i * out_side;

    float e0[9], e1[9];
    #pragma unroll
    for (int k = 0; k < 9; k++) {
        const int r = 3 * i + k / 3;
        const int c = 3 * j + (k - (k / 3) * 3);
        float f;
        if (FIRST) f = x[((size_t)b * in_side + r) * in_side + c];
        else       f = x[(r * in_side + c) * 128 + b];
        sincosf(f * PI_HALF, &e1[k], &e0[k]);
    }

    // v[a] = sum_p e[0][p] * W0[p, 0, a]
    float v[10];
    #pragma unroll
    for (int a = 0; a < 10; a++)
        v[a] = e0[0] * sW0[a] + e1[0] * sW0[10 + a];

    // 7 transfer-matrix steps: v <- v . M_s, M_s[a][c] = sum_p e[s+1][p]*Wm[s,a,p,c]
    #pragma unroll
    for (int s = 0; s < 7; s++) {
        const float* M = sWm + s * 200;   // [a(10)][p(2)][c(10)]
        float acc0[10], acc1[10];
        #pragma unroll
        for (int c = 0; c < 10; c++) { acc0[c] = 0.f; acc1[c] = 0.f; }
        #pragma unroll
        for (int a = 0; a < 10; a++) {
            const float va = v[a];
            const float* Ma = M + a * 20;   // 20 contiguous, 16B-aligned floats
            #pragma unroll
            for (int c = 0; c < 10; c++) {
                acc0[c] += va * Ma[c];
                acc1[c] += va * Ma[10 + c];
            }
        }
        const float ce = e0[s + 1], se = e1[s + 1];
        #pragma unroll
        for (int c = 0; c < 10; c++) v[c] = ce * acc0[c] + se * acc1[c];
    }

    // r[a] = Wn[a,0]*cos + Wn[a,1]*sin ; y = v . r
    float acc = 0.f;
    #pragma unroll
    for (int a = 0; a < 10; a++)
        acc += v[a] * (sWn[2 * a] * e0[8] + sWn[2 * a + 1] * e1[8]);

    y[n * 128 + b] = acc;
}

// Per-sample min-max normalization (batchnorm with V=1, g>0 is exactly
// absorbed by this min-max normalization, so it is skipped entirely).
// One block per sample. Reads/writes pixel-major [N,128].
__global__ void norm_k(const float* __restrict__ y, float* __restrict__ xo, int N)
{
    const int b = blockIdx.x;
    const int tid = threadIdx.x;

    float mn = INFINITY, mx = -INFINITY;
    for (int n = tid; n < N; n += 128) {
        const float v = y[n * 128 + b];
        mn = fminf(mn, v);
        mx = fmaxf(mx, v);
    }
    __shared__ float smn[128], smx[128];
    smn[tid] = mn; smx[tid] = mx;
    __syncthreads();
    #pragma unroll
    for (int s = 64; s > 0; s >>= 1) {
        if (tid < s) {
            smn[tid] = fminf(smn[tid], smn[tid + s]);
            smx[tid] = fmaxf(smx[tid], smx[tid + s]);
        }
        __syncthreads();
    }
    mn = smn[0]; mx = smx[0];
    const float inv = 1.0f / (mx - mn);
    for (int n = tid; n < N; n += 128)
        xo[n * 128 + b] = (y[n * 128 + b] - mn) * inv;
}

// Final layer: N=1 pixel, O=10 outputs. Block = output channel o, thread = sample b.
__global__ void mps_final(const float* __restrict__ x3,  // [9,128]
                          const float* __restrict__ W0,  // [1,2,10,10]
                          const float* __restrict__ Wm,  // [1,7,10,2,10]
                          const float* __restrict__ Wn,  // [1,10,2]
                          float* __restrict__ out)       // [128,10]
{
    __shared__ __align__(16) float sWm[1400];
    __shared__ float sW0[200];
    __shared__ float sWn[20];

    const int o = blockIdx.x;
    const int b = threadIdx.x;

    #pragma unroll
    for (int t = b; t < 1400; t += 128) sWm[t] = Wm[t];
    #pragma unroll
    for (int t = b; t < 200; t += 128) sW0[t] = W0[t];
    if (b < 20) sWn[b] = Wn[b];
    __syncthreads();

    float e0[9], e1[9];
    #pragma unroll
    for (int k = 0; k < 9; k++)
        sincosf(x3[k * 128 + b] * PI_HALF, &e1[k], &e0[k]);

    float v[10];
    #pragma unroll
    for (int a = 0; a < 10; a++)
        v[a] = e0[0] * sW0[o * 10 + a] + e1[0] * sW0[100 + o * 10 + a];

    #pragma unroll
    for (int s = 0; s < 7; s++) {
        const float* M = sWm + s * 200;
        float acc0[10], acc1[10];
        #pragma unroll
        for (int c = 0; c < 10; c++) { acc0[c] = 0.f; acc1[c] = 0.f; }
        #pragma unroll
        for (int a = 0; a < 10; a++) {
            const float va = v[a];
            const float* Ma = M + a * 20;
            #pragma unroll
            for (int c = 0; c < 10; c++) {
                acc0[c] += va * Ma[c];
                acc1[c] += va * Ma[10 + c];
            }
        }
        const float ce = e0[s + 1], se = e1[s + 1];
        #pragma unroll
        for (int c = 0; c < 10; c++) v[c] = ce * acc0[c] + se * acc1[c];
    }

    float acc = 0.f;
    #pragma unroll
    for (int a = 0; a < 10; a++)
        acc += v[a] * (sWn[2 * a] * e0[8] + sWn[2 * a + 1] * e1[8]);

    out[b * 10 + o] = acc;
}

extern "C" void kernel_launch(void* const* d_in, const int* in_sizes, int n_in,
                              void* d_out, int out_size)
{
    const float* x   = (const float*)d_in[0];
    const float* W00 = (const float*)d_in[1];
    const float* Wm0 = (const float*)d_in[2];
    const float* Wn0 = (const float*)d_in[3];
    const float* W01 = (const float*)d_in[6];
    const float* Wm1 = (const float*)d_in[7];
    const float* Wn1 = (const float*)d_in[8];
    const float* W02 = (const float*)d_in[11];
    const float* Wm2 = (const float*)d_in[12];
    const float* Wn2 = (const float*)d_in[13];
    const float* W03 = (const float*)d_in[16];
    const float* Wm3 = (const float*)d_in[17];
    const float* Wn3 = (const float*)d_in[18];
    float* out = (float*)d_out;

    float *y0, *x1, *y1, *x2, *y2, *x3;
    cudaGetSymbolAddress((void**)&y0, g_y0);
    cudaGetSymbolAddress((void**)&x1, g_x1);
    cudaGetSymbolAddress((void**)&y1, g_y1);
    cudaGetSymbolAddress((void**)&x2, g_x2);
    cudaGetSymbolAddress((void**)&y2, g_y2);
    cudaGetSymbolAddress((void**)&x3, g_x3);

    mps_small<true ><<<729, 128>>>(x,  W00, Wm0, Wn0, y0, 81, 27);
    norm_k<<<128, 128>>>(y0, x1, 729);
    mps_small<false><<<81,  128>>>(x1, W01, Wm1, Wn1, y1, 27, 9);
    norm_k<<<128, 128>>>(y1, x2, 81);
    mps_small<false><<<9,   128>>>(x2, W02, Wm2, Wn2, y2, 9, 3);
    norm_k<<<128, 128>>>(y2, x3, 9);
    mps_final<<<10, 128>>>(x3, W03, Wm3, Wn3, out);
}

// round 2
// speedup vs baseline: 1.2409x; 1.2409x over previous
#include <cuda_runtime.h>
#include <math.h>

#define PI_HALF 1.57079632679489662f
#define GRID 444
#define NT 128

// ---------------- scratch (pixel-major [N][B]) ----------------
__device__ float g_y0[729 * 128];
__device__ float g_y1[81 * 128];
__device__ float g_y2[9 * 128];
__device__ float g_mn0[128];
__device__ float g_inv0[128];

// ---------------- software grid barrier ----------------
// Self-resetting: g_count returns to 0 after every barrier, g_gen only used
// relatively (wrap-safe compare) -> deterministic across graph replays.
__device__ unsigned g_count = 0;
__device__ unsigned g_gen = 0;

__device__ __forceinline__ void grid_barrier()
{
    __threadfence();          // make this thread's global stores visible
    __syncthreads();          // all threads' stores ordered before arrival
    if (threadIdx.x == 0) {
        volatile unsigned* gen = &g_gen;
        const unsigned target = *gen + 1;
        const unsigned arrived = atomicAdd(&g_count, 1) + 1;
        if (arrived == GRID) {
            g_count = 0;
            __threadfence();
            atomicAdd(&g_gen, 1);
        } else {
            while ((int)(*gen - target) < 0) __nanosleep(32);
        }
        __threadfence();      // acquire: published data visible below
    }
    __syncthreads();
}

// ---------------- packed f32x2 FMA (Blackwell FFMA2) ----------------
__device__ __forceinline__ float2 ffma2(float2 a, float2 b, float2 c)
{
    unsigned long long au = *reinterpret_cast<unsigned long long*>(&a);
    unsigned long long bu = *reinterpret_cast<unsigned long long*>(&b);
    unsigned long long cu = *reinterpret_cast<unsigned long long*>(&c);
    unsigned long long du;
    asm("fma.rn.f32x2 %0, %1, %2, %3;" : "=l"(du) : "l"(au), "l"(bu), "l"(cu));
    return *reinterpret_cast<float2*>(&du);
}

// Stage Wm[n] (1400 floats, layout [s][a][p][c]) into smem permuted to
// [s][a][c][p] so the two p-channels are adjacent for packed FMA.
__device__ __forceinline__ void stage_wm(const float* __restrict__ gWm,
                                         float* __restrict__ sWm, int tid)
{
    #pragma unroll
    for (int t = tid; t < 1400; t += NT) {
        const int s  = t / 200;
        const int r  = t - s * 200;
        const int a  = r / 20;
        const int r2 = r - a * 20;
        const int p  = r2 / 10;
        const int c  = r2 - p * 10;
        sWm[s * 200 + a * 20 + c * 2 + p] = gWm[t];
    }
}

// Core MPS contraction. w0c/w0s: 10 floats each (cos / sin row of W0).
// sWm: permuted [7][10][10][2]. sWn: [10][2].
__device__ __forceinline__ float mps_core(const float* e0, const float* e1,
                                          const float* __restrict__ w0c,
                                          const float* __restrict__ w0s,
                                          const float* __restrict__ sWm,
                                          const float* __restrict__ sWn)
{
    float v[10];
    #pragma unroll
    for (int a = 0; a < 10; a++)
        v[a] = fmaf(e1[0], w0s[a], e0[0] * w0c[a]);

    #pragma unroll
    for (int s = 0; s < 7; s++) {
        const float2* M = reinterpret_cast<const float2*>(sWm) + s * 100;
        float2 acc[10];
        #pragma unroll
        for (int c = 0; c < 10; c++) acc[c] = make_float2(0.f, 0.f);
        #pragma unroll
        for (int a = 0; a < 10; a++) {
            const float2 va2 = make_float2(v[a], v[a]);
            const float2* Ma = M + a * 10;
            #pragma unroll
            for (int c = 0; c < 10; c++)
                acc[c] = ffma2(va2, Ma[c], acc[c]);
        }
        const float ce = e0[s + 1], se = e1[s + 1];
        #pragma unroll
        for (int c = 0; c < 10; c++)
            v[c] = fmaf(se, acc[c].y, ce * acc[c].x);
    }

    float r = 0.f;
    #pragma unroll
    for (int a = 0; a < 10; a++)
        r = fmaf(v[a], fmaf(e1[8], sWn[2 * a + 1], e0[8] * sWn[2 * a]), r);
    return r;
}

// ---------------- the single fused kernel ----------------
__global__ void __launch_bounds__(NT, 4)
fused_lotenet(const float* __restrict__ x,
              const float* __restrict__ W00, const float* __restrict__ Wm0, const float* __restrict__ Wn0,
              const float* __restrict__ W01, const float* __restrict__ Wm1, const float* __restrict__ Wn1,
              const float* __restrict__ W02, const float* __restrict__ Wm2, const float* __restrict__ Wn2,
              const float* __restrict__ W03, const float* __restrict__ Wm3, const float* __restrict__ Wn3,
              float* __restrict__ out)
{
    __shared__ __align__(16) float sWm[1400];
    __shared__ float sW0[200];
    __shared__ float sWn[20];
    __shared__ float sred[256];

    const int tid = threadIdx.x;   // sample b (for mps/norm phases)
    const int bid = blockIdx.x;

    float e0[9], e1[9];

    // ---- Phase 0: layer-0 MPS, 729 pixels, strided over 444 blocks ----
    for (int n = bid; n < 729; n += GRID) {
        __syncthreads();
        stage_wm(Wm0 + n * 1400, sWm, tid);
        if (tid < 20)      sW0[tid]      = W00[n * 20 + tid];
        else if (tid < 40) sWn[tid - 20] = Wn0[n * 20 + (tid - 20)];
        __syncthreads();

        const int i = n / 27, j = n - i * 27;
        #pragma unroll
        for (int k = 0; k < 9; k++) {
            const int r = 3 * i + k / 3;
            const int c = 3 * j + (k - (k / 3) * 3);
            const float f = x[((size_t)tid * 81 + r) * 81 + c];
            __sincosf(f * PI_HALF, &e1[k], &e0[k]);
        }
        g_y0[n * 128 + tid] = mps_core(e0, e1, sW0, sW0 + 10, sWm, sWn);
    }
    grid_barrier();

    // ---- Phase 1: per-sample min / 1/(max-min) over y0 (729) ----
    if (bid < 128) {
        float mn = INFINITY, mx = -INFINITY;
        for (int k = tid; k < 729; k += NT) {
            const float vv = g_y0[k * 128 + bid];
            mn = fminf(mn, vv);
            mx = fmaxf(mx, vv);
        }
        sred[tid] = mn; sred[128 + tid] = mx;
        __syncthreads();
        #pragma unroll
        for (int s = 64; s > 0; s >>= 1) {
            if (tid < s) {
                sred[tid]       = fminf(sred[tid], sred[tid + s]);
                sred[128 + tid] = fmaxf(sred[128 + tid], sred[128 + tid + s]);
            }
            __syncthreads();
        }
        if (tid == 0) {
            g_mn0[bid]  = sred[0];
            g_inv0[bid] = 1.0f / (sred[128] - sred[0]);
        }
    }
    grid_barrier();

    // ---- Phase 2: layer-1 MPS, 81 pixels (one block each) ----
    if (bid < 81) {
        const int n = bid;
        stage_wm(Wm1 + n * 1400, sWm, tid);
        if (tid < 20)      sW0[tid]      = W01[n * 20 + tid];
        else if (tid < 40) sWn[tid - 20] = Wn1[n * 20 + (tid - 20)];
        __syncthreads();

        const float mn = g_mn0[tid], iv = g_inv0[tid];
        const int i = n / 9, j = n - i * 9;
        #pragma unroll
        for (int k = 0; k < 9; k++) {
            const int r = 3 * i + k / 3;
            const int c = 3 * j + (k - (k / 3) * 3);
            const float f = (g_y0[(r * 27 + c) * 128 + tid] - mn) * iv;
            __sincosf(f * PI_HALF, &e1[k], &e0[k]);
        }
        g_y1[n * 128 + tid] = mps_core(e0, e1, sW0, sW0 + 10, sWm, sWn);
    }
    grid_barrier();

    // ---- Phase 3: layer-2 MPS, 9 pixels; norm over y1 folded in ----
    if (bid < 9) {
        const int n = bid;
        stage_wm(Wm2 + n * 1400, sWm, tid);
        if (tid < 20)      sW0[tid]      = W02[n * 20 + tid];
        else if (tid < 40) sWn[tid - 20] = Wn2[n * 20 + (tid - 20)];

        float mn = INFINITY, mx = -INFINITY;
        #pragma unroll 9
        for (int k = 0; k < 81; k++) {
            const float vv = g_y1[k * 128 + tid];
            mn = fminf(mn, vv);
            mx = fmaxf(mx, vv);
        }
        const float iv = 1.0f / (mx - mn);
        __syncthreads();

        const int i = n / 3, j = n - i * 3;
        #pragma unroll
        for (int k = 0; k < 9; k++) {
            const int r = 3 * i + k / 3;
            const int c = 3 * j + (k - (k / 3) * 3);
            const float f = (g_y1[(r * 9 + c) * 128 + tid] - mn) * iv;
            __sincosf(f * PI_HALF, &e1[k], &e0[k]);
        }
        g_y2[n * 128 + tid] = mps_core(e0, e1, sW0, sW0 + 10, sWm, sWn);
    }
    grid_barrier();

    // ---- Phase 4: final MPS (1 pixel, O=10); norm over y2 folded in ----
    if (bid < 10) {
        const int o = bid;
        stage_wm(Wm3, sWm, tid);
        #pragma unroll
        for (int t = tid; t < 200; t += NT) sW0[t] = W03[t];
        if (tid < 20) sWn[tid] = Wn3[tid];

        float mn = INFINITY, mx = -INFINITY;
        #pragma unroll
        for (int k = 0; k < 9; k++) {
            const float vv = g_y2[k * 128 + tid];
            mn = fminf(mn, vv);
            mx = fmaxf(mx, vv);
        }
        const float iv = 1.0f / (mx - mn);
        __syncthreads();

        #pragma unroll
        for (int k = 0; k < 9; k++) {
            const float f = (g_y2[k * 128 + tid] - mn) * iv;
            __sincosf(f * PI_HALF, &e1[k], &e0[k]);
        }
        out[tid * 10 + o] = mps_core(e0, e1, sW0 + o * 10, sW0 + 100 + o * 10, sWm, sWn);
    }
}

extern "C" void kernel_launch(void* const* d_in, const int* in_sizes, int n_in,
                              void* d_out, int out_size)
{
    const float* x   = (const float*)d_in[0];
    const float* W00 = (const float*)d_in[1];
    const float* Wm0 = (const float*)d_in[2];
    const float* Wn0 = (const float*)d_in[3];
    const float* W01 = (const float*)d_in[6];
    const float* Wm1 = (const float*)d_in[7];
    const float* Wn1 = (const float*)d_in[8];
    const float* W02 = (const float*)d_in[11];
    const float* Wm2 = (const float*)d_in[12];
    const float* Wn2 = (const float*)d_in[13];
    const float* W03 = (const float*)d_in[16];
    const float* Wm3 = (const float*)d_in[17];
    const float* Wn3 = (const float*)d_in[18];

    fused_lotenet<<<GRID, NT>>>(x, W00, Wm0, Wn0, W01, Wm1, Wn1,
                                W02, Wm2, Wn2, W03, Wm3, Wn3,
                                (float*)d_out);
}

// round 3
// speedup vs baseline: 1.4475x; 1.1665x over previous
#include <cuda_runtime.h>
#include <math.h>

#define PI_HALF 1.57079632679489662f
#define NT 128

// ---------------- scratch (pixel-major [N][B]) ----------------
__device__ float g_y0[729 * 128];
__device__ float g_y1[81 * 128];
__device__ float g_y2[9 * 128];

// Per-sample min/max atomic keys, 128B-padded (one L2 line per sample).
// Zero-initialized; key encoding chosen so 0 is the identity for atomicMax.
__device__ unsigned g_kx0[128 * 32];   // max key, layer 0
__device__ unsigned g_kn0[128 * 32];   // max ~key (== ~min key), layer 0
__device__ unsigned g_kx1[128 * 32];
__device__ unsigned g_kn1[128 * 32];

// ---------------- software grid barrier (self-resetting) ----------------
__device__ unsigned g_count = 0;
__device__ unsigned g_gen = 0;

__device__ __forceinline__ void grid_barrier()
{
    __threadfence();
    __syncthreads();
    if (threadIdx.x == 0) {
        volatile unsigned* gen = &g_gen;
        const unsigned target = *gen + 1;
        const unsigned arrived = atomicAdd(&g_count, 1) + 1;
        if (arrived == gridDim.x) {
            g_count = 0;
            __threadfence();
            atomicAdd(&g_gen, 1);
        } else {
            while ((int)(*gen - target) < 0) __nanosleep(32);
        }
        __threadfence();
    }
    __syncthreads();
}

// ---------------- monotonic float<->uint key (identity 0 for atomicMax) ----
__device__ __forceinline__ unsigned fkey(float f)
{
    unsigned u = __float_as_uint(f);
    return u ^ ((unsigned)((int)u >> 31) | 0x80000000u);
}
__device__ __forceinline__ float funkey(unsigned k)
{
    unsigned u = (k & 0x80000000u) ? (k ^ 0x80000000u) : ~k;
    return __uint_as_float(u);
}

// ---------------- packed f32x2 FMA (Blackwell FFMA2) ----------------
__device__ __forceinline__ float2 ffma2(float2 a, float2 b, float2 c)
{
    unsigned long long au = *reinterpret_cast<unsigned long long*>(&a);
    unsigned long long bu = *reinterpret_cast<unsigned long long*>(&b);
    unsigned long long cu = *reinterpret_cast<unsigned long long*>(&c);
    unsigned long long du;
    asm("fma.rn.f32x2 %0, %1, %2, %3;" : "=l"(du) : "l"(au), "l"(bu), "l"(cu));
    return *reinterpret_cast<float2*>(&du);
}

// Stage Wm[n] ([s][a][p][c], 1400 floats) into smem permuted so each a-row is
// 5 aligned float4s: element (p,c) -> a*20 + (c>>1)*4 + (c&1)*2 + p.
__device__ __forceinline__ void stage_wm(const float* __restrict__ gWm,
                                         float* __restrict__ sWm, int tid)
{
    #pragma unroll
    for (int t = tid; t < 1400; t += NT) {
        const int s  = t / 200;
        const int r  = t - s * 200;
        const int a  = r / 20;
        const int r2 = r - a * 20;
        const int p  = r2 / 10;
        const int c  = r2 - p * 10;
        sWm[s * 200 + a * 20 + ((c >> 1) << 2) + ((c & 1) << 1) + p] = gWm[t];
    }
}

// Core MPS contraction. sWm permuted as above; sWn [10][2].
__device__ __forceinline__ float mps_core(const float* e0, const float* e1,
                                          const float* __restrict__ w0c,
                                          const float* __restrict__ w0s,
                                          const float* __restrict__ sWm,
                                          const float* __restrict__ sWn)
{
    float v[10];
    #pragma unroll
    for (int a = 0; a < 10; a++)
        v[a] = fmaf(e1[0], w0s[a], e0[0] * w0c[a]);

    #pragma unroll
    for (int s = 0; s < 7; s++) {
        const float4* M = reinterpret_cast<const float4*>(sWm + s * 200);
        float2 acc[10];
        #pragma unroll
        for (int c = 0; c < 10; c++) acc[c] = make_float2(0.f, 0.f);
        #pragma unroll
        for (int a = 0; a < 10; a++) {
            const float2 va2 = make_float2(v[a], v[a]);
            const float4* Ma = M + a * 5;       // 5 float4 = 10 (p0,p1) pairs
            #pragma unroll
            for (int j = 0; j < 5; j++) {
                const float4 m = Ma[j];
                acc[2 * j]     = ffma2(va2, make_float2(m.x, m.y), acc[2 * j]);
                acc[2 * j + 1] = ffma2(va2, make_float2(m.z, m.w), acc[2 * j + 1]);
            }
        }
        const float ce = e0[s + 1], se = e1[s + 1];
        #pragma unroll
        for (int c = 0; c < 10; c++)
            v[c] = fmaf(se, acc[c].y, ce * acc[c].x);
    }

    float r = 0.f;
    #pragma unroll
    for (int a = 0; a < 10; a++)
        r = fmaf(v[a], fmaf(e1[8], sWn[2 * a + 1], e0[8] * sWn[2 * a]), r);
    return r;
}

// ---------------- single fused kernel ----------------
__global__ void __launch_bounds__(NT, 4)
fused_lotenet(const float* __restrict__ x,
              const float* __restrict__ W00, const float* __restrict__ Wm0, const float* __restrict__ Wn0,
              const float* __restrict__ W01, const float* __restrict__ Wm1, const float* __restrict__ Wn1,
              const float* __restrict__ W02, const float* __restrict__ Wm2, const float* __restrict__ Wn2,
              const float* __restrict__ W03, const float* __restrict__ Wm3, const float* __restrict__ Wn3,
              float* __restrict__ out)
{
    __shared__ __align__(16) float sWm[1400];
    __shared__ float sW0[200];
    __shared__ float sWn[20];

    const int tid = threadIdx.x;   // sample b
    const int bid = blockIdx.x;
    const int nblk = gridDim.x;

    float e0[9], e1[9];

    // ---- Phase 0: layer-0 MPS over 729 pixels; min/max folded via atomics ----
    {
        float lmn = INFINITY, lmx = -INFINITY;
        for (int n = bid; n < 729; n += nblk) {
            __syncthreads();
            stage_wm(Wm0 + n * 1400, sWm, tid);
            if (tid < 20)      sW0[tid]      = W00[n * 20 + tid];
            else if (tid < 40) sWn[tid - 20] = Wn0[n * 20 + (tid - 20)];
            __syncthreads();

            const int i = n / 27, j = n - i * 27;
            #pragma unroll
            for (int k = 0; k < 9; k++) {
                const int r = 3 * i + k / 3;
                const int c = 3 * j + (k - (k / 3) * 3);
                __sincosf(x[((size_t)tid * 81 + r) * 81 + c] * PI_HALF, &e1[k], &e0[k]);
            }
            const float y = mps_core(e0, e1, sW0, sW0 + 10, sWm, sWn);
            g_y0[n * 128 + tid] = y;
            lmn = fminf(lmn, y);
            lmx = fmaxf(lmx, y);
        }
        const unsigned kx = fkey(lmx), kn = ~fkey(lmn);
        atomicMax(&g_kx0[tid * 32], kx);
        atomicMax(&g_kn0[tid * 32], kn);
    }
    grid_barrier();

    // ---- Phase 1: layer-1 MPS, 81 pixels; reads layer-0 norm from keys ----
    if (bid < 81) {
        const int n = bid;
        stage_wm(Wm1 + n * 1400, sWm, tid);
        if (tid < 20)      sW0[tid]      = W01[n * 20 + tid];
        else if (tid < 40) sWn[tid - 20] = Wn1[n * 20 + (tid - 20)];

        const float mn = funkey(~g_kn0[tid * 32]);
        const float mx = funkey(g_kx0[tid * 32]);
        const float iv = 1.0f / (mx - mn);
        __syncthreads();

        const int i = n / 9, j = n - i * 9;
        #pragma unroll
        for (int k = 0; k < 9; k++) {
            const int r = 3 * i + k / 3;
            const int c = 3 * j + (k - (k / 3) * 3);
            const float f = (g_y0[(r * 27 + c) * 128 + tid] - mn) * iv;
            __sincosf(f * PI_HALF, &e1[k], &e0[k]);
        }
        const float y = mps_core(e0, e1, sW0, sW0 + 10, sWm, sWn);
        g_y1[n * 128 + tid] = y;
        atomicMax(&g_kx1[tid * 32], fkey(y));
        atomicMax(&g_kn1[tid * 32], ~fkey(y));
    }
    grid_barrier();

    // ---- Phase 2: layer-2 MPS, 9 pixels; reads layer-1 norm from keys.
    //      Block 16 (idle here) resets layer-0 keys for the next replay. ----
    if (bid < 9) {
        const int n = bid;
        stage_wm(Wm2 + n * 1400, sWm, tid);
        if (tid < 20)      sW0[tid]      = W02[n * 20 + tid];
        else if (tid < 40) sWn[tid - 20] = Wn2[n * 20 + (tid - 20)];

        const float mn = funkey(~g_kn1[tid * 32]);
        const float mx = funkey(g_kx1[tid * 32]);
        const float iv = 1.0f / (mx - mn);
        __syncthreads();

        const int i = n / 3, j = n - i * 3;
        #pragma unroll
        for (int k = 0; k < 9; k++) {
            const int r = 3 * i + k / 3;
            const int c = 3 * j + (k - (k / 3) * 3);
            const float f = (g_y1[(r * 9 + c) * 128 + tid] - mn) * iv;
            __sincosf(f * PI_HALF, &e1[k], &e0[k]);
        }
        g_y2[n * 128 + tid] = mps_core(e0, e1, sW0, sW0 + 10, sWm, sWn);
    } else if (bid == 16) {
        g_kx0[tid * 32] = 0;
        g_kn0[tid * 32] = 0;
    }
    grid_barrier();

    // ---- Phase 3: final MPS (1 pixel, O=10); norm over y2 (9 vals) inline.
    //      Block 16 resets layer-1 keys. ----
    if (bid < 10) {
        const int o = bid;
        stage_wm(Wm3, sWm, tid);
        #pragma unroll
        for (int t = tid; t < 200; t += NT) sW0[t] = W03[t];
        if (tid < 20) sWn[tid] = Wn3[tid];

        float yk[9];
        float mn = INFINITY, mx = -INFINITY;
        #pragma unroll
        for (int k = 0; k < 9; k++) {
            yk[k] = g_y2[k * 128 + tid];
            mn = fminf(mn, yk[k]);
            mx = fmaxf(mx, yk[k]);
        }
        const float iv = 1.0f / (mx - mn);
        __syncthreads();

        #pragma unroll
        for (int k = 0; k < 9; k++)
            __sincosf((yk[k] - mn) * iv * PI_HALF, &e1[k], &e0[k]);

        out[tid * 10 + o] = mps_core(e0, e1, sW0 + o * 10, sW0 + 100 + o * 10, sWm, sWn);
    } else if (bid == 16) {
        g_kx1[tid * 32] = 0;
        g_kn1[tid * 32] = 0;
    }
}

extern "C" void kernel_launch(void* const* d_in, const int* in_sizes, int n_in,
                              void* d_out, int out_size)
{
    const float* x   = (const float*)d_in[0];
    const float* W00 = (const float*)d_in[1];
    const float* Wm0 = (const float*)d_in[2];
    const float* Wn0 = (const float*)d_in[3];
    const float* W01 = (const float*)d_in[6];
    const float* Wm1 = (const float*)d_in[7];
    const float* Wn1 = (const float*)d_in[8];
    const float* W02 = (const float*)d_in[11];
    const float* Wm2 = (const float*)d_in[12];
    const float* Wn2 = (const float*)d_in[13];
    const float* W03 = (const float*)d_in[16];
    const float* Wm3 = (const float*)d_in[17];
    const float* Wn3 = (const float*)d_in[18];

    int nsm = 148;
    cudaDeviceGetAttribute(&nsm, cudaDevAttrMultiProcessorCount, 0);
    const int grid = 4 * nsm;   // __launch_bounds__(128,4) guarantees residency

    fused_lotenet<<<grid, NT>>>(x, W00, Wm0, Wn0, W01, Wm1, Wn1,
                                W02, Wm2, Wn2, W03, Wm3, Wn3,
                                (float*)d_out);
}